// round 7
// baseline (speedup 1.0000x reference)
#include <cuda_runtime.h>
#include <cuda_bf16.h>
#include <mma.h>
#include <cstdint>

using namespace nvcuda;

#define N_MAX 100000
#define E_MAX 1000000
#define NB_MAX 128            // ceil(N_MAX/1024) = 98

// ---------------- device scratch (static; device-side references only) ----------------
__device__ int g_cnt[N_MAX];
__device__ int g_rowptr[N_MAX + 1];
__device__ int g_cursor[N_MAX];
__device__ int g_csr[E_MAX];
__device__ int g_bsum[NB_MAX];
__device__ __nv_bfloat16 g_xh[(size_t)N_MAX * 64];
__device__ __nv_bfloat16 g_xl[(size_t)N_MAX * 64];
__device__ __nv_bfloat16 g_hh[(size_t)N_MAX * 64];
__device__ __nv_bfloat16 g_hl[(size_t)N_MAX * 64];
__device__ float g_yl[(size_t)N_MAX * 64];   // lin_l projection (gathered by agg)
__device__ float g_yr[(size_t)N_MAX * 64];   // lin_r projection (root)
__device__ __align__(16) __nv_bfloat16 g_wh[2][8192];  // W' = [W_l;W_r], [128 n][64 k] row-major, bf16 hi
__device__ __align__(16) __nv_bfloat16 g_wl[2][8192];  // bf16 lo

// ---------------- CSR build ----------------
__global__ void zero_k(int n) {
    int i = blockIdx.x * blockDim.x + threadIdx.x;
    if (i < n) g_cnt[i] = 0;
}

__global__ void count_k(const int* __restrict__ dst, int e, int n) {
    int i = blockIdx.x * blockDim.x + threadIdx.x;
    if (i < e) {
        int d = dst[i];
        if ((unsigned)d < (unsigned)n) atomicAdd(&g_cnt[d], 1);
    }
}

__global__ void scan1_k(int n) {
    int base = blockIdx.x * 1024;
    int t = threadIdx.x;
    int i0 = base + t * 4;
    int s = 0;
#pragma unroll
    for (int j = 0; j < 4; j++) {
        int i = i0 + j;
        if (i < n) s += g_cnt[i];
    }
#pragma unroll
    for (int o = 16; o; o >>= 1) s += __shfl_down_sync(0xffffffffu, s, o);
    __shared__ int ws[8];
    if ((t & 31) == 0) ws[t >> 5] = s;
    __syncthreads();
    if (t == 0) {
        int tot = 0;
#pragma unroll
        for (int j = 0; j < 8; j++) tot += ws[j];
        g_bsum[blockIdx.x] = tot;
    }
}

// merged scan2+scan3: each block derives its exclusive base from g_bsum itself
__global__ void scan23_k(int n, int e) {
    int t = threadIdx.x;
    int bid = blockIdx.x;
    int val = (t < bid) ? g_bsum[t] : 0;   // bid <= 97 < 256
#pragma unroll
    for (int o = 16; o; o >>= 1) val += __shfl_down_sync(0xffffffffu, val, o);
    __shared__ int wsb[8];
    __shared__ int s_base;
    if ((t & 31) == 0) wsb[t >> 5] = val;
    __syncthreads();
    if (t == 0) {
        int b = 0;
#pragma unroll
        for (int j = 0; j < 8; j++) b += wsb[j];
        s_base = b;
        if (bid == 0) g_rowptr[n] = e;
    }
    __syncthreads();
    int base = s_base;

    int lane = t & 31, wid = t >> 5;
    int i0 = bid * 1024 + t * 4;
    int v[4];
    int tsum = 0;
#pragma unroll
    for (int j = 0; j < 4; j++) {
        v[j] = (i0 + j < n) ? g_cnt[i0 + j] : 0;
        tsum += v[j];
    }
    int incl = tsum;
#pragma unroll
    for (int o = 1; o < 32; o <<= 1) {
        int u = __shfl_up_sync(0xffffffffu, incl, o);
        if (lane >= o) incl += u;
    }
    __shared__ int ws[8];
    if (lane == 31) ws[wid] = incl;
    __syncthreads();
    if (t < 8) {
        int u = ws[t];
        int inc = u;
#pragma unroll
        for (int o = 1; o < 8; o <<= 1) {
            int q = __shfl_up_sync(0xffu, inc, o);
            if (t >= o) inc += q;
        }
        ws[t] = inc - u;
    }
    __syncthreads();
    int excl = incl - tsum + ws[wid] + base;
#pragma unroll
    for (int j = 0; j < 4; j++) {
        int i = i0 + j;
        if (i < n) {
            g_rowptr[i] = excl;
            g_cursor[i] = excl;
            excl += v[j];
        }
    }
}

__global__ void fill_k(const int* __restrict__ src, const int* __restrict__ dst, int e, int n) {
    int i = blockIdx.x * blockDim.x + threadIdx.x;
    if (i < e) {
        int d = dst[i];
        int s = src[i];
        if ((unsigned)d < (unsigned)n && (unsigned)s < (unsigned)n) {
            int pos = atomicAdd(&g_cursor[d], 1);
            g_csr[pos] = s;
        }
    }
}

// ---------------- x -> bf16 hi/lo split ----------------
__global__ void conv_k(const float* __restrict__ x, int npairs) {
    int i = blockIdx.x * blockDim.x + threadIdx.x;
    if (i >= npairs) return;
    float2 v = ((const float2*)x)[i];
    __nv_bfloat16 h0 = __float2bfloat16(v.x);
    __nv_bfloat16 h1 = __float2bfloat16(v.y);
    __nv_bfloat16 l0 = __float2bfloat16(v.x - __bfloat162float(h0));
    __nv_bfloat16 l1 = __float2bfloat16(v.y - __bfloat162float(h1));
    ((__nv_bfloat162*)g_xh)[i] = __nv_bfloat162(h0, h1);
    ((__nv_bfloat162*)g_xl)[i] = __nv_bfloat162(l0, l1);
}

// ---------------- W' = [W_l ; W_r] (128 x 64, row-major) -> bf16 hi/lo ----------------
__global__ void wsplit_k(const float* __restrict__ W1l, const float* __restrict__ W1r,
                         const float* __restrict__ W2l, const float* __restrict__ W2r) {
    int id = blockIdx.x * blockDim.x + threadIdx.x;
    if (id >= 16384) return;
    int l = id >> 13;
    int rem = id & 8191;
    int nr = rem >> 6;    // 0..127 output row
    int k = rem & 63;     // 0..63 input col
    const float* Wl = l ? W2l : W1l;
    const float* Wr = l ? W2r : W1r;
    float w = (nr < 64) ? Wl[nr * 64 + k] : Wr[(nr - 64) * 64 + k];
    __nv_bfloat16 hi = __float2bfloat16(w);
    __nv_bfloat16 lo = __float2bfloat16(w - __bfloat162float(hi));
    g_wh[l][nr * 64 + k] = hi;
    g_wl[l][nr * 64 + k] = lo;
}

// ---------------- WMMA GEMM: y[m0:m0+128][0:128] = A(hi,lo) @ W'(hi,lo)^T ----------------
// 3-term compensated bf16: Ah*Wh + Ah*Wl + Al*Wh, fp32 accumulation.
// 256 threads = 8 warps; warp w computes rows [m0+16w, m0+16w+16) x 128 cols.
// A hi/lo in smem, pitch 72 bf16 (36 words == 4 mod 32 -> conflict-free ldmatrix).
#define AP 72

template <int L>
__global__ void __launch_bounds__(256)
gemm_k(int n) {
    __shared__ __nv_bfloat16 Ah_s[128 * AP];
    __shared__ __nv_bfloat16 Al_s[128 * AP];
    __shared__ float C_s[8 * 256];   // boundary staging, per-warp 16x16

    int tid = threadIdx.x;
    int w = tid >> 5;
    int lane = tid & 31;
    int m0 = blockIdx.x * 128;

    const uint32_t* __restrict__ srch = (const uint32_t*)(L ? g_hh : g_xh);
    const uint32_t* __restrict__ srcl = (const uint32_t*)(L ? g_hl : g_xl);

    // stage A tile (128 rows x 64 bf16 = 32 u32/row), zero-pad OOB rows
    for (int idx = tid; idx < 4096; idx += 256) {
        int row = idx >> 5;
        int c = idx & 31;
        int gm = m0 + row;
        uint32_t vh = 0u, vl = 0u;
        if (gm < n) {
            vh = srch[(size_t)gm * 32 + c];
            vl = srcl[(size_t)gm * 32 + c];
        }
        ((uint32_t*)Ah_s)[row * (AP / 2) + c] = vh;
        ((uint32_t*)Al_s)[row * (AP / 2) + c] = vl;
    }
    __syncthreads();

    const __nv_bfloat16* __restrict__ Wh = g_wh[L];
    const __nv_bfloat16* __restrict__ Wl = g_wl[L];

    wmma::fragment<wmma::accumulator, 16, 16, 16, float> acc[8];
#pragma unroll
    for (int nt = 0; nt < 8; nt++) wmma::fill_fragment(acc[nt], 0.0f);

#pragma unroll
    for (int kt = 0; kt < 4; kt++) {
        wmma::fragment<wmma::matrix_a, 16, 16, 16, __nv_bfloat16, wmma::row_major> ah, al;
        wmma::load_matrix_sync(ah, &Ah_s[(w * 16) * AP + kt * 16], AP);
        wmma::load_matrix_sync(al, &Al_s[(w * 16) * AP + kt * 16], AP);
#pragma unroll
        for (int nt = 0; nt < 8; nt++) {
            wmma::fragment<wmma::matrix_b, 16, 16, 16, __nv_bfloat16, wmma::col_major> bh, bl;
            // B tile: k in [16kt,16kt+16), n in [16nt,16nt+16); stored W'[n][k], ld=64
            wmma::load_matrix_sync(bh, Wh + (nt * 16) * 64 + kt * 16, 64);
            wmma::load_matrix_sync(bl, Wl + (nt * 16) * 64 + kt * 16, 64);
            wmma::mma_sync(acc[nt], ah, bh, acc[nt]);
            wmma::mma_sync(acc[nt], ah, bl, acc[nt]);
            wmma::mma_sync(acc[nt], al, bh, acc[nt]);
        }
    }

    int r0 = m0 + w * 16;
    if (r0 + 16 <= n) {
        // fast path: direct stores
#pragma unroll
        for (int nt = 0; nt < 8; nt++) {
            float* base = ((nt < 4) ? g_yl : g_yr) + (size_t)r0 * 64 + (nt & 3) * 16;
            wmma::store_matrix_sync(base, acc[nt], 64, wmma::mem_row_major);
        }
    } else if (r0 < n) {
        // boundary: stage per-warp, guarded copy
        float* stage = C_s + w * 256;
#pragma unroll
        for (int nt = 0; nt < 8; nt++) {
            wmma::store_matrix_sync(stage, acc[nt], 16, wmma::mem_row_major);
            __syncwarp();
            float* base = ((nt < 4) ? g_yl : g_yr);
#pragma unroll
            for (int q = 0; q < 8; q++) {
                int idx = lane * 8 + q;
                int row = idx >> 4;
                int col = idx & 15;
                int gm = r0 + row;
                if (gm < n) base[(size_t)gm * 64 + (nt & 3) * 16 + col] = stage[idx];
            }
            __syncwarp();
        }
    }
}

// ---------------- aggregation + epilogue: warp per node ----------------
// val = mean-gather(g_yl) + g_yr[own] + bias; L=0: relu + bf16 hi/lo split, L=1: fp32 out
template <int L>
__global__ void __launch_bounds__(256)
aggf_k(const float* __restrict__ bias, float* __restrict__ outp, int n) {
    int w = (blockIdx.x * 256 + threadIdx.x) >> 5;
    int lane = threadIdx.x & 31;
    if (w >= n) return;
    int beg = g_rowptr[w], end = g_rowptr[w + 1];
    float a0 = 0.f, a1 = 0.f;
    int p = beg;
    for (; p + 3 < end; p += 4) {
        int s0 = g_csr[p], s1 = g_csr[p + 1], s2 = g_csr[p + 2], s3 = g_csr[p + 3];
        const float* r0 = g_yl + (size_t)s0 * 64;
        const float* r1 = g_yl + (size_t)s1 * 64;
        const float* r2 = g_yl + (size_t)s2 * 64;
        const float* r3 = g_yl + (size_t)s3 * 64;
        a0 += (r0[lane] + r1[lane]) + (r2[lane] + r3[lane]);
        a1 += (r0[lane + 32] + r1[lane + 32]) + (r2[lane + 32] + r3[lane + 32]);
    }
    for (; p < end; p++) {
        const float* r = g_yl + (size_t)g_csr[p] * 64;
        a0 += r[lane];
        a1 += r[lane + 32];
    }
    int deg = end - beg;
    float inv = (deg > 0) ? (1.f / (float)deg) : 0.f;
    float v0 = fmaf(a0, inv, g_yr[(size_t)w * 64 + lane] + bias[lane]);
    float v1 = fmaf(a1, inv, g_yr[(size_t)w * 64 + 32 + lane] + bias[lane + 32]);
    if (L == 0) {
        v0 = fmaxf(v0, 0.f);
        v1 = fmaxf(v1, 0.f);
        __nv_bfloat16 h0 = __float2bfloat16(v0);
        __nv_bfloat16 h1 = __float2bfloat16(v1);
        g_hh[(size_t)w * 64 + lane] = h0;
        g_hh[(size_t)w * 64 + 32 + lane] = h1;
        g_hl[(size_t)w * 64 + lane] = __float2bfloat16(v0 - __bfloat162float(h0));
        g_hl[(size_t)w * 64 + 32 + lane] = __float2bfloat16(v1 - __bfloat162float(h1));
    } else {
        outp[(size_t)w * 64 + lane] = v0;
        outp[(size_t)w * 64 + 32 + lane] = v1;
    }
}

// ---------------- launcher ----------------
extern "C" void kernel_launch(void* const* d_in, const int* in_sizes, int n_in,
                              void* d_out, int out_size) {
    const float* x   = (const float*)d_in[0];
    const int*   ei  = (const int*)d_in[1];   // int32 (JAX x64 disabled)
    const float* W1l = (const float*)d_in[2];
    const float* b1  = (const float*)d_in[3];
    const float* W1r = (const float*)d_in[4];
    const float* W2l = (const float*)d_in[5];
    const float* b2  = (const float*)d_in[6];
    const float* W2r = (const float*)d_in[7];
    float* out = (float*)d_out;

    int n = in_sizes[0] / 64;
    int e = in_sizes[1] / 2;
    if (n > N_MAX) n = N_MAX;
    if (e > E_MAX) e = E_MAX;

    const int* src = ei;
    const int* dst = ei + e;
    int nb = (n + 1023) / 1024;

    // CSR build (by dst)
    zero_k<<<(n + 255) / 256, 256>>>(n);
    count_k<<<(e + 255) / 256, 256>>>(dst, e, n);
    scan1_k<<<nb, 256>>>(n);
    scan23_k<<<nb, 256>>>(n, e);
    fill_k<<<(e + 255) / 256, 256>>>(src, dst, e, n);

    // input/weight bf16 splits
    conv_k<<<(n * 32 + 255) / 256, 256>>>(x, n * 32);
    wsplit_k<<<64, 256>>>(W1l, W1r, W2l, W2r);

    int gg = (n + 127) / 128;
    int ga = (n + 7) / 8;

    // Layer 1: y = x@[W1l|W1r]^T ; h = relu(mean-gather(yl) + yr + b1) -> bf16 split
    gemm_k<0><<<gg, 256>>>(n);
    aggf_k<0><<<ga, 256>>>(b1, nullptr, n);

    // Layer 2: y = h@[W2l|W2r]^T ; out = mean-gather(yl) + yr + b2
    gemm_k<1><<<gg, 256>>>(n);
    aggf_k<1><<<ga, 256>>>(b2, out, n);
}

// round 8
// speedup vs baseline: 1.4567x; 1.4567x over previous
#include <cuda_runtime.h>
#include <cuda_bf16.h>
#include <mma.h>
#include <cstdint>

using namespace nvcuda;

#define N_MAX 100000
#define E_MAX 1000000
#define NB_MAX 128            // ceil(N_MAX/1024) = 98
#define NPAD (N_MAX + 128)    // feature rows padded so edge-tile wmma loads stay in-bounds

// ---------------- device scratch (static; device-side references only) ----------------
__device__ int g_cnt[N_MAX];
__device__ int g_rowptr[N_MAX + 1];
__device__ int g_cursor[N_MAX];
__device__ int g_csr[E_MAX];
__device__ int g_bsum[NB_MAX];
__device__ __nv_bfloat16 g_xh[(size_t)NPAD * 64];
__device__ __nv_bfloat16 g_xl[(size_t)NPAD * 64];
__device__ __nv_bfloat16 g_hh[(size_t)NPAD * 64];
__device__ __nv_bfloat16 g_hl[(size_t)NPAD * 64];
__device__ float g_yl[(size_t)N_MAX * 64];   // lin_l projection (gathered by agg)
__device__ float g_yr[(size_t)N_MAX * 64];   // lin_r projection (root)
// W' = [W_l;W_r] TRANSPOSED: [64 k][128 n] row-major, bf16 hi/lo
__device__ __align__(16) __nv_bfloat16 g_wth[2][8192];
__device__ __align__(16) __nv_bfloat16 g_wtl[2][8192];

// ---------------- CSR build ----------------
__global__ void zero_k(int n) {
    int i = blockIdx.x * blockDim.x + threadIdx.x;
    if (i < n) g_cnt[i] = 0;
}

__global__ void count_k(const int* __restrict__ dst, int e, int n) {
    int i = blockIdx.x * blockDim.x + threadIdx.x;
    if (i < e) {
        int d = dst[i];
        if ((unsigned)d < (unsigned)n) atomicAdd(&g_cnt[d], 1);
    }
}

__global__ void scan1_k(int n) {
    int base = blockIdx.x * 1024;
    int t = threadIdx.x;
    int i0 = base + t * 4;
    int s = 0;
#pragma unroll
    for (int j = 0; j < 4; j++) {
        int i = i0 + j;
        if (i < n) s += g_cnt[i];
    }
#pragma unroll
    for (int o = 16; o; o >>= 1) s += __shfl_down_sync(0xffffffffu, s, o);
    __shared__ int ws[8];
    if ((t & 31) == 0) ws[t >> 5] = s;
    __syncthreads();
    if (t == 0) {
        int tot = 0;
#pragma unroll
        for (int j = 0; j < 8; j++) tot += ws[j];
        g_bsum[blockIdx.x] = tot;
    }
}

// merged scan2+scan3: each block derives its exclusive base from g_bsum itself
__global__ void scan23_k(int n, int e) {
    int t = threadIdx.x;
    int bid = blockIdx.x;
    int val = (t < bid) ? g_bsum[t] : 0;   // bid <= 97 < 256
#pragma unroll
    for (int o = 16; o; o >>= 1) val += __shfl_down_sync(0xffffffffu, val, o);
    __shared__ int wsb[8];
    __shared__ int s_base;
    if ((t & 31) == 0) wsb[t >> 5] = val;
    __syncthreads();
    if (t == 0) {
        int b = 0;
#pragma unroll
        for (int j = 0; j < 8; j++) b += wsb[j];
        s_base = b;
        if (bid == 0) g_rowptr[n] = e;
    }
    __syncthreads();
    int base = s_base;

    int lane = t & 31, wid = t >> 5;
    int i0 = bid * 1024 + t * 4;
    int v[4];
    int tsum = 0;
#pragma unroll
    for (int j = 0; j < 4; j++) {
        v[j] = (i0 + j < n) ? g_cnt[i0 + j] : 0;
        tsum += v[j];
    }
    int incl = tsum;
#pragma unroll
    for (int o = 1; o < 32; o <<= 1) {
        int u = __shfl_up_sync(0xffffffffu, incl, o);
        if (lane >= o) incl += u;
    }
    __shared__ int ws[8];
    if (lane == 31) ws[wid] = incl;
    __syncthreads();
    if (t < 8) {
        int u = ws[t];
        int inc = u;
#pragma unroll
        for (int o = 1; o < 8; o <<= 1) {
            int q = __shfl_up_sync(0xffu, inc, o);
            if (t >= o) inc += q;
        }
        ws[t] = inc - u;
    }
    __syncthreads();
    int excl = incl - tsum + ws[wid] + base;
#pragma unroll
    for (int j = 0; j < 4; j++) {
        int i = i0 + j;
        if (i < n) {
            g_rowptr[i] = excl;
            g_cursor[i] = excl;
            excl += v[j];
        }
    }
}

__global__ void fill_k(const int* __restrict__ src, const int* __restrict__ dst, int e, int n) {
    int i = blockIdx.x * blockDim.x + threadIdx.x;
    if (i < e) {
        int d = dst[i];
        int s = src[i];
        if ((unsigned)d < (unsigned)n && (unsigned)s < (unsigned)n) {
            int pos = atomicAdd(&g_cursor[d], 1);
            g_csr[pos] = s;
        }
    }
}

// ---------------- x -> bf16 hi/lo split ----------------
__global__ void conv_k(const float* __restrict__ x, int npairs) {
    int i = blockIdx.x * blockDim.x + threadIdx.x;
    if (i >= npairs) return;
    float2 v = ((const float2*)x)[i];
    __nv_bfloat16 h0 = __float2bfloat16(v.x);
    __nv_bfloat16 h1 = __float2bfloat16(v.y);
    __nv_bfloat16 l0 = __float2bfloat16(v.x - __bfloat162float(h0));
    __nv_bfloat16 l1 = __float2bfloat16(v.y - __bfloat162float(h1));
    ((__nv_bfloat162*)g_xh)[i] = __nv_bfloat162(h0, h1);
    ((__nv_bfloat162*)g_xl)[i] = __nv_bfloat162(l0, l1);
}

// ---------------- W' = [W_l ; W_r] -> TRANSPOSED [64 k][128 n] bf16 hi/lo ----------------
__global__ void wsplit_k(const float* __restrict__ W1l, const float* __restrict__ W1r,
                         const float* __restrict__ W2l, const float* __restrict__ W2r) {
    int id = blockIdx.x * blockDim.x + threadIdx.x;
    if (id >= 16384) return;
    int l = id >> 13;
    int rem = id & 8191;
    int nr = rem >> 6;    // 0..127 output row of W'
    int k = rem & 63;     // 0..63 input col
    const float* Wl = l ? W2l : W1l;
    const float* Wr = l ? W2r : W1r;
    float w = (nr < 64) ? Wl[nr * 64 + k] : Wr[(nr - 64) * 64 + k];
    __nv_bfloat16 hi = __float2bfloat16(w);
    __nv_bfloat16 lo = __float2bfloat16(w - __bfloat162float(hi));
    g_wth[l][k * 128 + nr] = hi;     // transposed store
    g_wtl[l][k * 128 + nr] = lo;
}

// ---------------- WMMA GEMM: y[m0:m0+128][0:128] = A(hi,lo) @ W'(hi,lo)^T ----------------
// 3-term compensated bf16: Ah*Wh + Ah*Wl + Al*Wh, fp32 accumulation.
// 256 threads = 8 warps; warp w computes rows [m0+16w, m0+16w+16) x 128 cols.
// A fragments loaded straight from global bf16 (8 per warp, L1-resident rows).
// W staged in smem pitch 136 (68 words = 4 mod 32 -> conflict-free ldmatrix).
#define WP 136

template <int L>
__global__ void __launch_bounds__(256)
gemm_k(int n) {
    __shared__ __nv_bfloat16 Wh_s[64 * WP];
    __shared__ __nv_bfloat16 Wl_s[64 * WP];
    __shared__ float C_s[8 * 256];   // boundary staging only

    int tid = threadIdx.x;
    int w = tid >> 5;
    int lane = tid & 31;
    int m0 = blockIdx.x * 128;

    // stage W tiles (each 64 rows x 128 bf16 = 64 u32/row)
    {
        const uint32_t* __restrict__ sh = (const uint32_t*)g_wth[L];
        const uint32_t* __restrict__ sl = (const uint32_t*)g_wtl[L];
        uint32_t* dh = (uint32_t*)Wh_s;
        uint32_t* dl = (uint32_t*)Wl_s;
#pragma unroll
        for (int idx = tid; idx < 4096; idx += 256) {
            int row = idx >> 6;
            int c = idx & 63;
            dh[row * (WP / 2) + c] = sh[idx];
            dl[row * (WP / 2) + c] = sl[idx];
        }
    }
    __syncthreads();

    const __nv_bfloat16* __restrict__ Ah = (L ? g_hh : g_xh);
    const __nv_bfloat16* __restrict__ Al = (L ? g_hl : g_xl);
    int r0 = m0 + w * 16;
    const __nv_bfloat16* arow_h = Ah + (size_t)r0 * 64;
    const __nv_bfloat16* arow_l = Al + (size_t)r0 * 64;

    wmma::fragment<wmma::accumulator, 16, 16, 16, float> acc[8];
#pragma unroll
    for (int nt = 0; nt < 8; nt++) wmma::fill_fragment(acc[nt], 0.0f);

#pragma unroll
    for (int kt = 0; kt < 4; kt++) {
        wmma::fragment<wmma::matrix_a, 16, 16, 16, __nv_bfloat16, wmma::row_major> ah, al;
        wmma::load_matrix_sync(ah, arow_h + kt * 16, 64);
        wmma::load_matrix_sync(al, arow_l + kt * 16, 64);
#pragma unroll
        for (int nt = 0; nt < 8; nt++) {
            wmma::fragment<wmma::matrix_b, 16, 16, 16, __nv_bfloat16, wmma::row_major> bh, bl;
            wmma::load_matrix_sync(bh, &Wh_s[(kt * 16) * WP + nt * 16], WP);
            wmma::load_matrix_sync(bl, &Wl_s[(kt * 16) * WP + nt * 16], WP);
            wmma::mma_sync(acc[nt], ah, bh, acc[nt]);
            wmma::mma_sync(acc[nt], ah, bl, acc[nt]);
            wmma::mma_sync(acc[nt], al, bh, acc[nt]);
        }
    }

    if (r0 + 16 <= n) {
        // fast path: direct stores
#pragma unroll
        for (int nt = 0; nt < 8; nt++) {
            float* base = ((nt < 4) ? g_yl : g_yr) + (size_t)r0 * 64 + (nt & 3) * 16;
            wmma::store_matrix_sync(base, acc[nt], 64, wmma::mem_row_major);
        }
    } else if (r0 < n) {
        // boundary: stage per-warp, guarded copy
        float* stage = C_s + w * 256;
#pragma unroll
        for (int nt = 0; nt < 8; nt++) {
            wmma::store_matrix_sync(stage, acc[nt], 16, wmma::mem_row_major);
            __syncwarp();
            float* base = ((nt < 4) ? g_yl : g_yr);
#pragma unroll
            for (int q = 0; q < 8; q++) {
                int idx = lane * 8 + q;
                int row = idx >> 4;
                int col = idx & 15;
                int gm = r0 + row;
                if (gm < n) base[(size_t)gm * 64 + (nt & 3) * 16 + col] = stage[idx];
            }
            __syncwarp();
        }
    }
}

// ---------------- aggregation + epilogue: warp per node ----------------
// val = mean-gather(g_yl) + g_yr[own] + bias; L=0: relu + bf16 hi/lo split, L=1: fp32 out
template <int L>
__global__ void __launch_bounds__(256)
aggf_k(const float* __restrict__ bias, float* __restrict__ outp, int n) {
    int w = (blockIdx.x * 256 + threadIdx.x) >> 5;
    int lane = threadIdx.x & 31;
    if (w >= n) return;
    int beg = g_rowptr[w], end = g_rowptr[w + 1];
    float a0 = 0.f, a1 = 0.f;
    int p = beg;
    for (; p + 3 < end; p += 4) {
        int s0 = g_csr[p], s1 = g_csr[p + 1], s2 = g_csr[p + 2], s3 = g_csr[p + 3];
        const float* r0 = g_yl + (size_t)s0 * 64;
        const float* r1 = g_yl + (size_t)s1 * 64;
        const float* r2 = g_yl + (size_t)s2 * 64;
        const float* r3 = g_yl + (size_t)s3 * 64;
        a0 += (r0[lane] + r1[lane]) + (r2[lane] + r3[lane]);
        a1 += (r0[lane + 32] + r1[lane + 32]) + (r2[lane + 32] + r3[lane + 32]);
    }
    for (; p < end; p++) {
        const float* r = g_yl + (size_t)g_csr[p] * 64;
        a0 += r[lane];
        a1 += r[lane + 32];
    }
    int deg = end - beg;
    float inv = (deg > 0) ? (1.f / (float)deg) : 0.f;
    float v0 = fmaf(a0, inv, g_yr[(size_t)w * 64 + lane] + bias[lane]);
    float v1 = fmaf(a1, inv, g_yr[(size_t)w * 64 + 32 + lane] + bias[lane + 32]);
    if (L == 0) {
        v0 = fmaxf(v0, 0.f);
        v1 = fmaxf(v1, 0.f);
        __nv_bfloat16 h0 = __float2bfloat16(v0);
        __nv_bfloat16 h1 = __float2bfloat16(v1);
        g_hh[(size_t)w * 64 + lane] = h0;
        g_hh[(size_t)w * 64 + 32 + lane] = h1;
        g_hl[(size_t)w * 64 + lane] = __float2bfloat16(v0 - __bfloat162float(h0));
        g_hl[(size_t)w * 64 + 32 + lane] = __float2bfloat16(v1 - __bfloat162float(h1));
    } else {
        outp[(size_t)w * 64 + lane] = v0;
        outp[(size_t)w * 64 + 32 + lane] = v1;
    }
}

// ---------------- launcher ----------------
extern "C" void kernel_launch(void* const* d_in, const int* in_sizes, int n_in,
                              void* d_out, int out_size) {
    const float* x   = (const float*)d_in[0];
    const int*   ei  = (const int*)d_in[1];   // int32 (JAX x64 disabled)
    const float* W1l = (const float*)d_in[2];
    const float* b1  = (const float*)d_in[3];
    const float* W1r = (const float*)d_in[4];
    const float* W2l = (const float*)d_in[5];
    const float* b2  = (const float*)d_in[6];
    const float* W2r = (const float*)d_in[7];
    float* out = (float*)d_out;

    int n = in_sizes[0] / 64;
    int e = in_sizes[1] / 2;
    if (n > N_MAX) n = N_MAX;
    if (e > E_MAX) e = E_MAX;

    const int* src = ei;
    const int* dst = ei + e;
    int nb = (n + 1023) / 1024;
    int gg = (n + 127) / 128;
    int ga = (n + 7) / 8;

    // NOTE: launch order places gemm_k<0> at slot 4 so ncu (-s 5 -c 1) captures it.
    // gemm0 depends only on conv + wsplit; CSR build is independent of it.
    conv_k<<<(n * 32 + 255) / 256, 256>>>(x, n * 32);          // 1
    wsplit_k<<<64, 256>>>(W1l, W1r, W2l, W2r);                 // 2
    zero_k<<<(n + 255) / 256, 256>>>(n);                       // 3
    gemm_k<0><<<gg, 256>>>(n);                                 // 4  <- profiled
    count_k<<<(e + 255) / 256, 256>>>(dst, e, n);              // 5
    scan1_k<<<nb, 256>>>(n);                                   // 6
    scan23_k<<<nb, 256>>>(n, e);                               // 7
    fill_k<<<(e + 255) / 256, 256>>>(src, dst, e, n);          // 8

    // Layer 1 epilogue: h = relu(mean-gather(yl) + yr + b1) -> bf16 split
    aggf_k<0><<<ga, 256>>>(b1, nullptr, n);                    // 9
    // Layer 2
    gemm_k<1><<<gg, 256>>>(n);                                 // 10
    aggf_k<1><<<ga, 256>>>(b2, out, n);                        // 11
}